// round 4
// baseline (speedup 1.0000x reference)
#include <cuda_runtime.h>
#include <math.h>
#include <stddef.h>

#define RS 507904  /* max rows (992) * 512 */

__device__ float g_W0[1024];
__device__ float g_PE[16384];
__device__ float g_GCS[4096];
__device__ float g_Y[524288];
__device__ float g_QKV[3*RS];
__device__ float g_AB[RS];
__device__ float g_H1[RS];
__device__ float g_H2[RS];
__device__ float g_XB[RS];
__device__ float g_LOG[320000];
__device__ unsigned g_count;
__device__ volatile unsigned g_sense;

// ------------------------- grid-wide barrier -------------------------------
__device__ __forceinline__ void gsync()
{
    __threadfence();
    __syncthreads();
    if (threadIdx.x == 0) {
        unsigned gen = g_sense;
        if (atomicAdd(&g_count, 1u) == gridDim.x - 1) {
            g_count = 0;
            __threadfence();
            g_sense = gen + 1;
        } else {
            while (g_sense == gen) __nanosleep(32);
        }
    }
    __syncthreads();
    __threadfence();
}

// --------------------- GEMM helpers (tile: 8 x 512, K=512) -----------------
__device__ __forceinline__ void load_A8(const float* __restrict__ src, int fromY,
                                        int cur, int r0, float* __restrict__ As)
{
#pragma unroll
    for (int it = 0; it < 4; ++it) {
        int lin = it*256 + threadIdx.x;
        int row = lin >> 7, c4 = lin & 127;
        int gr = r0 + row;
        const float* rp;
        if (fromY) { int b = gr/cur, s = gr - b*cur; rp = src + b*16384 + s*512; }
        else        rp = src + (size_t)gr*512;
        ((float4*)As)[row*128 + c4] = ((const float4*)rp)[c4];
    }
}

__device__ __forceinline__ void mm8(const float* __restrict__ Wp,
                                    const float* __restrict__ As,
                                    float* __restrict__ Ws, float acc[4][4])
{
    int ty = threadIdx.x >> 7;
    int cg = threadIdx.x & 127;
    for (int k0 = 0; k0 < 512; k0 += 8) {
        __syncthreads();
#pragma unroll
        for (int it = 0; it < 4; ++it) {
            int lin = it*256 + threadIdx.x;
            ((float4*)Ws)[lin] =
                ((const float4*)(Wp + (size_t)(k0 + (lin >> 7))*512))[lin & 127];
        }
        __syncthreads();
#pragma unroll
        for (int kk = 0; kk < 8; ++kk) {
            float4 w4 = ((const float4*)(Ws + kk*512))[cg];
            float a0 = As[(ty*4+0)*512 + k0 + kk];
            float a1 = As[(ty*4+1)*512 + k0 + kk];
            float a2 = As[(ty*4+2)*512 + k0 + kk];
            float a3 = As[(ty*4+3)*512 + k0 + kk];
            acc[0][0]+=a0*w4.x; acc[0][1]+=a0*w4.y; acc[0][2]+=a0*w4.z; acc[0][3]+=a0*w4.w;
            acc[1][0]+=a1*w4.x; acc[1][1]+=a1*w4.y; acc[1][2]+=a1*w4.z; acc[1][3]+=a1*w4.w;
            acc[2][0]+=a2*w4.x; acc[2][1]+=a2*w4.y; acc[2][2]+=a2*w4.z; acc[2][3]+=a2*w4.w;
            acc[3][0]+=a3*w4.x; acc[3][1]+=a3*w4.y; acc[3][2]+=a3*w4.z; acc[3][3]+=a3*w4.w;
        }
    }
    __syncthreads();
}

__device__ __forceinline__ void acc_to_smem(float acc[4][4], const float* __restrict__ bias,
                                            float* __restrict__ Cs, int relu)
{
    int ty = threadIdx.x >> 7, cg = threadIdx.x & 127;
    float4 bb = ((const float4*)bias)[cg];
#pragma unroll
    for (int i = 0; i < 4; ++i) {
        float4 o;
        o.x = acc[i][0]+bb.x; o.y = acc[i][1]+bb.y;
        o.z = acc[i][2]+bb.z; o.w = acc[i][3]+bb.w;
        if (relu) { o.x=fmaxf(o.x,0.f); o.y=fmaxf(o.y,0.f);
                    o.z=fmaxf(o.z,0.f); o.w=fmaxf(o.w,0.f); }
        ((float4*)(Cs + (ty*4+i)*512))[cg] = o;
    }
}

__device__ __forceinline__ void acc_to_global(float acc[4][4], const float* __restrict__ bias,
                                              float* __restrict__ C, int r0)
{
    int ty = threadIdx.x >> 7, cg = threadIdx.x & 127;
    float4 bb = ((const float4*)bias)[cg];
#pragma unroll
    for (int i = 0; i < 4; ++i) {
        int r = r0 + ty*4 + i;
        float4 o;
        o.x = acc[i][0]+bb.x; o.y = acc[i][1]+bb.y;
        o.z = acc[i][2]+bb.z; o.w = acc[i][3]+bb.w;
        ((float4*)(C + (size_t)r*512))[cg] = o;
    }
}

// LN over (Cs_row + res_row) -> outb, one warp per row (8 rows)
__device__ __forceinline__ void ln_rows(const float* __restrict__ Cs,
                                        const float* __restrict__ resbase, int resFromY,
                                        int cur, int r0,
                                        const float* __restrict__ gma,
                                        const float* __restrict__ bta,
                                        float* __restrict__ outb)
{
    int w = threadIdx.x >> 5, l = threadIdx.x & 31;
    int gr = r0 + w;
    const float* res;
    if (resFromY) { int b = gr/cur, s = gr - b*cur; res = resbase + b*16384 + s*512; }
    else           res = resbase + (size_t)gr*512;

    float v[16]; float s = 0.f;
#pragma unroll
    for (int j = 0; j < 16; ++j) {
        v[j] = Cs[w*512 + j*32 + l] + res[j*32 + l];
        s += v[j];
    }
#pragma unroll
    for (int o = 16; o; o >>= 1) s += __shfl_xor_sync(0xffffffffu, s, o);
    float mean = s * (1.f/512.f);
    float vs = 0.f;
#pragma unroll
    for (int j = 0; j < 16; ++j) { float d = v[j] - mean; vs += d*d; }
#pragma unroll
    for (int o = 16; o; o >>= 1) vs += __shfl_xor_sync(0xffffffffu, vs, o);
    float inv = rsqrtf(vs * (1.f/512.f) + 1e-5f);
    float* op = outb + (size_t)gr*512;
#pragma unroll
    for (int j = 0; j < 16; ++j) {
        int c = j*32 + l;
        op[c] = gma[c]*(v[j]-mean)*inv + bta[c];
    }
}

// Collapsed cross-attn, in place on Cs (8 q-rows x 512)
__device__ __forceinline__ void cross_transform(float* __restrict__ Cs, int r0, int cur,
                                                int n, const float* __restrict__ bca)
{
    int w = threadIdx.x >> 5, l = threadIdx.x & 31;
    int gr = r0 + w;
    int b = gr / cur;
    float wl = (l < cur) ? g_W0[b*32 + l] : 0.f;
    const float* csk = g_GCS + (n*2+0)*512;
    const float* csv = g_GCS + (n*2+1)*512;
    const float* bv  = bca + (size_t)(n*4+2)*512;

    float dh[8];
#pragma unroll
    for (int h = 0; h < 8; ++h) dh[h] = 0.f;
#pragma unroll
    for (int j = 0; j < 16; ++j) {
        int c = j*32 + l;
        dh[j>>1] += Cs[w*512 + c] * csk[c];
    }
    float wb[8];
#pragma unroll
    for (int h = 0; h < 8; ++h) {
        float A = dh[h];
#pragma unroll
        for (int o = 16; o; o >>= 1) A += __shfl_xor_sync(0xffffffffu, A, o);
        A *= 0.125f;
        float z = (l < cur) ? A*wl : -3.0e38f;
        float mx = z;
#pragma unroll
        for (int o = 16; o; o >>= 1) mx = fmaxf(mx, __shfl_xor_sync(0xffffffffu, mx, o));
        float e = (l < cur) ? expf(z - mx) : 0.f;
        float se = e, sw = e*wl;
#pragma unroll
        for (int o = 16; o; o >>= 1) {
            se += __shfl_xor_sync(0xffffffffu, se, o);
            sw += __shfl_xor_sync(0xffffffffu, sw, o);
        }
        wb[h] = sw / se;
    }
#pragma unroll
    for (int j = 0; j < 16; ++j) {
        int c = j*32 + l;
        Cs[w*512 + c] = wb[j>>1]*csv[c] + bv[c];
    }
}

// ------------------------------- megakernel --------------------------------
__global__ void __launch_bounds__(256, 1)
mega(const float* __restrict__ noise, const float* __restrict__ W_in,
     const float* __restrict__ b_in, const float* __restrict__ emb,
     const float* __restrict__ Wsa, const float* __restrict__ bsa,
     const float* __restrict__ Wca, const float* __restrict__ bca,
     const float* __restrict__ Wff, const float* __restrict__ bff,
     const float* __restrict__ ln_g, const float* __restrict__ ln_b,
     const float* __restrict__ soft_W, const float* __restrict__ soft_b,
     float* __restrict__ out)
{
    __shared__ float smem[12288];           // 48KB: As | Ws | Cs
    float* As = smem;
    float* Ws = smem + 4096;
    float* Cs = smem + 8192;
    int tid = threadIdx.x, bid = blockIdx.x;
    int grid = gridDim.x;
    int gt = bid*256 + tid, gs = grid*256;

    // =============================== setup ================================
    if (bid == 0) {
        float* s0 = smem; float* s1 = smem + 1024;
        for (int i = tid; i < 1024; i += 256) s0[i] = noise[i];
        __syncthreads();
        for (int m = 0; m < 2; ++m) {
            for (int i = tid; i < 1024; i += 256) {
                int r = i >> 5, c = i & 31;
                float a = b_in[m*32 + c];
#pragma unroll
                for (int k = 0; k < 32; ++k) a += s0[r*32+k]*W_in[m*1024 + k*32 + c];
                s1[i] = a;
            }
            __syncthreads();
            float* t = s0; s0 = s1; s1 = t;
            __syncthreads();
        }
        for (int i = tid; i < 1024; i += 256) g_W0[i] = s0[i];
    }
    for (int i = gt; i < 16384; i += gs) {                  // pos encoding
        int s = i >> 9, e = i & 511;
        float div = expf((float)(e & ~1) * (-logf(10000.0f)/512.0f));
        float ang = (float)s * div;
        g_PE[i] = (e & 1) ? cosf(ang) : sinf(ang);
    }
    for (int i = gt; i < 4096; i += gs) {                   // colsums of Wk,Wv
        int n2w = i >> 9, j = i & 511;
        int n = n2w >> 1, which = n2w & 1;
        const float* Wp = Wca + (size_t)(n*4 + 1 + which)*262144 + j;
        float a = 0.f;
        for (int e = 0; e < 512; ++e) a += Wp[(size_t)e*512];
        g_GCS[i] = a;
    }
    for (int i = gt; i < 16384; i += gs) {                  // Y[:,0,:]
        int b = i >> 9, e = i & 511;
        g_Y[b*16384 + e] = emb[e] + ((e & 1) ? 1.f : 0.f);  // pe[0]: sin0/cos0
    }
    for (int i = gt; i < 320000; i += gs) {                 // out[:,0,:]
        int b = i / 10000, v = i - b*10000;
        out[(size_t)b*320000 + v] = (v == 0) ? 1.f : 0.f;
    }
    gsync();

    // ============================ token loop ==============================
    for (int tok = 1; tok < 32; ++tok) {
        int cur = tok, rows = 32*cur, ntr = rows >> 3;
        for (int n = 0; n < 4; ++n) {
            int fromY = (n == 0);
            const float* Xsrc = fromY ? g_Y : g_XB;

            // ---- S1: QKV GEMMs ----
            for (int tile = bid; tile < 3*ntr; tile += grid) {
                int which = tile / ntr, rt = tile - which*ntr, r0 = rt*8;
                __syncthreads();
                load_A8(Xsrc, fromY, cur, r0, As);
                float acc[4][4] = {};
                mm8(Wsa + (size_t)(n*4 + which)*262144, As, Ws, acc);
                acc_to_global(acc, bsa + (size_t)(n*4 + which)*512,
                              g_QKV + (size_t)which*RS, r0);
            }
            gsync();

            // ---- S1b: self attention ----
            for (int p = bid; p < 256; p += grid) {
                int b = p >> 3, h = p & 7;
                float* sk = smem; float* sv = smem + 2048;
                __syncthreads();
                for (int idx = tid; idx < cur*64; idx += 256) {
                    int t = idx >> 6, d = idx & 63;
                    size_t off = (size_t)(b*cur + t)*512 + h*64 + d;
                    sk[idx] = g_QKV[RS + off];
                    sv[idx] = g_QKV[2*(size_t)RS + off];
                }
                __syncthreads();
                int warp = tid >> 5, l = tid & 31;
                for (int t = warp; t < cur; t += 8) {
                    const float* qp = g_QKV + (size_t)(b*cur + t)*512 + h*64;
                    float q0 = qp[l], q1 = qp[l+32];
                    float my = -3.0e38f;
                    for (int j = 0; j < cur; ++j) {
                        float s = q0*sk[j*64+l] + q1*sk[j*64+l+32];
#pragma unroll
                        for (int o = 16; o; o >>= 1) s += __shfl_xor_sync(0xffffffffu, s, o);
                        if (l == j) my = s*0.125f;
                    }
                    float mx = (l < cur) ? my : -3.0e38f;
#pragma unroll
                    for (int o = 16; o; o >>= 1) mx = fmaxf(mx, __shfl_xor_sync(0xffffffffu, mx, o));
                    float pp = (l < cur) ? expf(my - mx) : 0.f;
                    float sum = pp;
#pragma unroll
                    for (int o = 16; o; o >>= 1) sum += __shfl_xor_sync(0xffffffffu, sum, o);
                    pp /= sum;
                    float a0 = 0.f, a1 = 0.f;
                    for (int j = 0; j < cur; ++j) {
                        float pj = __shfl_sync(0xffffffffu, pp, j);
                        a0 += pj*sv[j*64+l];
                        a1 += pj*sv[j*64+l+32];
                    }
                    float* op = g_AB + (size_t)(b*cur + t)*512 + h*64;
                    op[l] = a0; op[l+32] = a1;
                }
            }
            gsync();

            // ---- S2: attn out-proj + residual LN -> H1 ----
            for (int rt = bid; rt < ntr; rt += grid) {
                int r0 = rt*8;
                __syncthreads();
                load_A8(g_AB, 0, cur, r0, As);
                float acc[4][4] = {};
                mm8(Wsa + (size_t)(n*4+3)*262144, As, Ws, acc);
                acc_to_smem(acc, bsa + (size_t)(n*4+3)*512, Cs, 0);
                __syncthreads();
                ln_rows(Cs, Xsrc, fromY, cur, r0,
                        ln_g + (size_t)(n*3)*512, ln_b + (size_t)(n*3)*512, g_H1);
            }
            gsync();

            // ---- S3: cross-attn chain -> H2 ----
            for (int rt = bid; rt < ntr; rt += grid) {
                int r0 = rt*8;
                __syncthreads();
                load_A8(g_H1, 0, cur, r0, As);
                float acc[4][4] = {};
                mm8(Wca + (size_t)(n*4+0)*262144, As, Ws, acc);
                acc_to_smem(acc, bca + (size_t)(n*4+0)*512, Cs, 0);
                __syncthreads();
                cross_transform(Cs, r0, cur, n, bca);
                __syncthreads();
                float acc2[4][4] = {};
                mm8(Wca + (size_t)(n*4+3)*262144, Cs, Ws, acc2);
                acc_to_smem(acc2, bca + (size_t)(n*4+3)*512, As, 0);
                __syncthreads();
                ln_rows(As, g_H1, 0, cur, r0,
                        ln_g + (size_t)(n*3+1)*512, ln_b + (size_t)(n*3+1)*512, g_H2);
            }
            gsync();

            // ---- S4: FFN chain -> XB ----
            for (int rt = bid; rt < ntr; rt += grid) {
                int r0 = rt*8;
                __syncthreads();
                load_A8(g_H2, 0, cur, r0, As);
                float acc[4][4] = {};
                mm8(Wff + (size_t)(n*2+0)*262144, As, Ws, acc);
                acc_to_smem(acc, bff + (size_t)(n*2+0)*512, Cs, 1);
                __syncthreads();
                float acc2[4][4] = {};
                mm8(Wff + (size_t)(n*2+1)*262144, Cs, Ws, acc2);
                acc_to_smem(acc2, bff + (size_t)(n*2+1)*512, As, 0);
                __syncthreads();
                ln_rows(As, g_H2, 0, cur, r0,
                        ln_g + (size_t)(n*3+2)*512, ln_b + (size_t)(n*3+2)*512, g_XB);
            }
            gsync();
        }

        // ---- logits: xtok(32x512) @ soft_W(512x10000) + soft_b ----
        for (int tile = bid; tile < 157; tile += grid) {
            int ty = tid >> 6, ci = tid & 63;
            int col = tile*64 + ci;
            int valid = (col < 10000);
            float acc[8];
#pragma unroll
            for (int i = 0; i < 8; ++i) acc[i] = 0.f;
            for (int k0 = 0; k0 < 512; k0 += 256) {
                __syncthreads();
#pragma unroll
                for (int it = 0; it < 8; ++it) {
                    int lin = it*256 + tid;
                    int r = lin >> 6, kq = lin & 63;
                    ((float4*)smem)[lin] =
                        ((const float4*)(g_XB + (size_t)(r*cur + cur-1)*512 + k0))[kq];
                }
                __syncthreads();
                for (int kk = 0; kk < 256; ++kk) {
                    float wv = valid ? soft_W[(size_t)(k0+kk)*10000 + col] : 0.f;
#pragma unroll
                    for (int i = 0; i < 8; ++i)
                        acc[i] += smem[(ty*8+i)*256 + kk] * wv;
                }
            }
            if (valid) {
                float sb = soft_b[col];
#pragma unroll
                for (int i = 0; i < 8; ++i)
                    g_LOG[(size_t)(ty*8+i)*10000 + col] = acc[i] + sb;
            }
        }
        gsync();

        // ---- softmax + argmax + next token (one CTA per b) ----
        for (int b = bid; b < 32; b += grid) {
            __syncthreads();
            const float* lg = g_LOG + (size_t)b*10000;
            float* sv = smem;
            int* si = (int*)(smem + 256);
            float mx = -3.0e38f; int mi = 0;
            for (int c = tid; c < 10000; c += 256) {
                float v = lg[c];
                if (v > mx) { mx = v; mi = c; }
            }
            sv[tid] = mx; si[tid] = mi;
            __syncthreads();
            for (int st = 128; st; st >>= 1) {
                if (tid < st) {
                    float v2 = sv[tid+st]; int i2 = si[tid+st];
                    if (v2 > sv[tid] || (v2 == sv[tid] && i2 < si[tid])) { sv[tid] = v2; si[tid] = i2; }
                }
                __syncthreads();
            }
            float gmax = sv[0];
            int id = si[0];
            __syncthreads();
            float s = 0.f;
            for (int c = tid; c < 10000; c += 256) s += expf(lg[c] - gmax);
            sv[tid] = s;
            __syncthreads();
            for (int st = 128; st; st >>= 1) {
                if (tid < st) sv[tid] += sv[tid+st];
                __syncthreads();
            }
            float inv = 1.f / sv[0];
            float* op = out + (size_t)b*320000 + (size_t)tok*10000;
            for (int c = tid; c < 10000; c += 256) op[c] = expf(lg[c] - gmax)*inv;
            // next token embedding
            for (int e = tid; e < 512; e += 256)
                g_Y[b*16384 + tok*512 + e] = emb[(size_t)id*512 + e] + g_PE[tok*512 + e];
        }
        gsync();
    }
}

// ---------------------------------------------------------------------------
extern "C" void kernel_launch(void* const* d_in, const int* in_sizes, int n_in,
                              void* d_out, int out_size)
{
    const float* noise  = (const float*)d_in[0];
    const float* W_in   = (const float*)d_in[1];
    const float* b_in   = (const float*)d_in[2];
    const float* emb    = (const float*)d_in[3];
    const float* Wsa    = (const float*)d_in[4];
    const float* bsa    = (const float*)d_in[5];
    const float* Wca    = (const float*)d_in[6];
    const float* bca    = (const float*)d_in[7];
    const float* Wff    = (const float*)d_in[8];
    const float* bff    = (const float*)d_in[9];
    const float* ln_g   = (const float*)d_in[10];
    const float* ln_b   = (const float*)d_in[11];
    const float* soft_W = (const float*)d_in[12];
    const float* soft_b = (const float*)d_in[13];
    float* out = (float*)d_out;

    int dev = 0, sms = 148;
    cudaGetDevice(&dev);
    cudaDeviceGetAttribute(&sms, cudaDevAttrMultiProcessorCount, dev);
    if (sms < 32) sms = 32;

    mega<<<sms, 256>>>(noise, W_in, b_in, emb, Wsa, bsa, Wca, bca,
                       Wff, bff, ln_g, ln_b, soft_W, soft_b, out);
}